// round 13
// baseline (speedup 1.0000x reference)
#include <cuda_runtime.h>
#include <math.h>

// ---------------------------------------------------------------------------
//  B=4096, SEQ=C=8, D=4, L=2048, NK=256, NCLS=100
//  filters: w3 (256,3,2048), w4 (256,4,2048), w5 (256,5,2048) -> 3072 rows
// ---------------------------------------------------------------------------

#define NKK 3072
#define NCLS 100

#define NB_GEMV 384
#define NB_IDX  1024
#define NB_K2   256
#define NB_K3   1024
#define NB_TOT  (NB_GEMV + NB_IDX + NB_K2 + NB_K3)   // 2688

__device__ float    g_WeFp[2 * 5 * NKK];            // [half][d][nkk]; d=4 = be
__device__ __align__(16) float g_V[8 * 16 * NCLS];  // 16B-aligned for float4
__device__ unsigned g_code[4096];                   // packed idx: 8 x 4 bits
__device__ int      c_gemv, c_idx, c_k2, c_exit;    // phase counters (reset each run)

__device__ __forceinline__ void phase_done(int tid, int* ctr) {
    __threadfence();
    __syncthreads();
    if (tid == 0) atomicAdd(ctr, 1);
}

__device__ __forceinline__ void phase_wait2(int tid, int* c1, int t1, int* c2, int t2) {
    if (tid == 0) {
        while (((volatile int*)c1)[0] < t1 || ((volatile int*)c2)[0] < t2)
            __nanosleep(64);
    }
    __syncthreads();
    __threadfence();
}

// ---------------------------------------------------------------------------
// Megakernel: 2688 blocks x 128 threads. Phases via counters; CTAs issue in
// index order so waiters always follow their producers (no circular wait).
// ---------------------------------------------------------------------------
__global__ void __launch_bounds__(128, 4)
mega(const float* __restrict__ We, const float* __restrict__ be,
     const float* __restrict__ w3, const float* __restrict__ w4,
     const float* __restrict__ w5, const void* __restrict__ xraw,
     const float* __restrict__ len_emb, const float* __restrict__ ipd_emb,
     const float* __restrict__ W1, const float* __restrict__ b1,
     const float* __restrict__ S,  const float* __restrict__ T,
     const float* __restrict__ H,  const float* __restrict__ LUT,
     const float* __restrict__ W2, const float* __restrict__ b2,
     float* __restrict__ out)
{
    __shared__ float4 sW4[5 * 256];   // 20 KB, reused per phase
    const int tid  = threadIdx.x;
    const int lane = tid & 31;
    const int warp = tid >> 5;
    const int bx   = blockIdx.x;

    if (bx < NB_GEMV) {
        // ==================== GEMV (round-8 structure) =======================
        const int grp = bx >> 1;
        const int ch  = bx & 1;
        const int r0  = grp * 16 + warp * 4;

        const float4* rp[4];
        #pragma unroll
        for (int r = 0; r < 4; r++) {
            int rid = r0 + r;
            int n = rid / 12, kk = rid % 12;
            const float* base;
            if (kk < 3)      base = w3 + (size_t)(n * 3 + kk) * 2048;
            else if (kk < 7) base = w4 + (size_t)(n * 4 + (kk - 3)) * 2048;
            else             base = w5 + (size_t)(n * 5 + (kk - 7)) * 2048;
            rp[r] = (const float4*)base + ch * 256;
        }

        float4 bufA[4], bufB[4];
        #pragma unroll
        for (int r = 0; r < 4; r++) bufA[r] = rp[r][lane];

        const float4* We4 = (const float4*)We;
        const float4* be4 = (const float4*)be;
        #pragma unroll
        for (int i = 0; i < 2; i++) {
            const int p = tid + 128 * i;
            sW4[p]        = We4[ch * 256 + p];
            sW4[256 + p]  = We4[512 + ch * 256 + p];
            sW4[512 + p]  = We4[1024 + ch * 256 + p];
            sW4[768 + p]  = We4[1536 + ch * 256 + p];
            sW4[1024 + p] = be4[ch * 256 + p];
        }
        __syncthreads();

        float acc[4][5];
        #pragma unroll
        for (int r = 0; r < 4; r++)
            #pragma unroll
            for (int d = 0; d < 5; d++) acc[r][d] = 0.f;

        #pragma unroll
        for (int i = 0; i < 8; i++) {
            float4* cur = (i & 1) ? bufB : bufA;
            float4* nxt = (i & 1) ? bufA : bufB;
            if (i < 7) {
                const int o = (i + 1) * 32 + lane;
                #pragma unroll
                for (int r = 0; r < 4; r++) nxt[r] = rp[r][o];
            }
            const int l = i * 32 + lane;
            #pragma unroll
            for (int d = 0; d < 5; d++) {
                float4 s = sW4[d * 256 + l];
                #pragma unroll
                for (int r = 0; r < 4; r++)
                    acc[r][d] += cur[r].x * s.x + cur[r].y * s.y
                               + cur[r].z * s.z + cur[r].w * s.w;
            }
        }

        #pragma unroll
        for (int r = 0; r < 4; r++)
            #pragma unroll
            for (int d = 0; d < 5; d++) {
                float a = acc[r][d];
                #pragma unroll
                for (int w = 16; w > 0; w >>= 1)
                    a += __shfl_down_sync(0xffffffffu, a, w);
                if (lane == 0)
                    g_WeFp[ch * 5 * NKK + d * NKK + (r0 + r)] = a;
            }

        phase_done(tid, &c_gemv);

    } else if (bx < NB_GEMV + NB_IDX) {
        // ==================== g_V zeroing + idx codes ========================
        const int lb = bx - NB_GEMV;   // 0..1023
        float* sf = (float*)sW4;       // [0:128) W1, [128:132) b1, [132:612) S,
                                       // [612:732) T, [732:972) H
        sf[tid] = W1[tid];
        if (tid < 4) sf[128 + tid] = b1[tid];
        #pragma unroll
        for (int i = 0; i < 4; i++) {
            int p = tid + 128 * i;
            if (p < 480) sf[132 + p] = S[p];
        }
        if (tid < 120) sf[612 + tid] = T[tid];
        sf[732 + tid] = H[tid];
        if (tid < 112) sf[860 + tid] = H[128 + tid];

        {
            int gz = lb * 128 + tid;
            if (gz < 8 * 16 * NCLS) g_V[gz] = 0.f;
        }
        __syncthreads();

        const int b = lb * 4 + warp;   // 0..4095

        const int* xi = (const int*)xraw;
        int any = 0;
        #pragma unroll
        for (int j = 0; j < 4; j++) any |= xi[1 + 2 * (lane + 32 * j)];
        const int is64 = __any_sync(0xffffffffu, any != 0) ? 0 : 1;

        const int c = lane >> 2;
        const int q = lane & 3;

        int i0, i1;
        if (is64) {
            const long long* xp = (const long long*)xraw;
            i0 = (int)xp[((size_t)b * 8 + c) * 2];
            i1 = (int)xp[((size_t)b * 8 + c) * 2 + 1];
        } else {
            const int* xp = (const int*)xraw;
            i0 = xp[((size_t)b * 8 + c) * 2];
            i1 = xp[((size_t)b * 8 + c) * 2 + 1];
        }

        float4 vl = ((const float4*)(len_emb + (size_t)i0 * 16))[q];
        float4 vi = ((const float4*)(ipd_emb + (size_t)i1 * 16))[q];

        float h4[4] = {0.f, 0.f, 0.f, 0.f};
        {
            const float lv[4] = {vl.x, vl.y, vl.z, vl.w};
            const float iv[4] = {vi.x, vi.y, vi.z, vi.w};
            #pragma unroll
            for (int s = 0; s < 4; s++) {
                const int il = q * 4 + s;
                const int ii = 16 + q * 4 + s;
                #pragma unroll
                for (int d = 0; d < 4; d++) {
                    h4[d] += lv[s] * sf[il * 4 + d];
                    h4[d] += iv[s] * sf[ii * 4 + d];
                }
            }
        }
        #pragma unroll
        for (int d = 0; d < 4; d++) {
            h4[d] += __shfl_xor_sync(0xffffffffu, h4[d], 1);
            h4[d] += __shfl_xor_sync(0xffffffffu, h4[d], 2);
            h4[d] += sf[128 + d];
        }

        float m16[16];
        #pragma unroll
        for (int j = 0; j < 16; j++) m16[j] = 0.f;

        #pragma unroll
        for (int kq = 0; kq < 4; kq++) {
            const int k = q + kq * 4;
            if (k < 15) {
                float a = 0.f;
                #pragma unroll
                for (int d = 0; d < 4; d++)
                    a += h4[d] * sf[132 + (c * 4 + d) * 15 + k];
                float m = (a - sf[612 + c * 15 + k]) - 1e-4f;
                float sgn = (m > 0.f) ? 1.f : ((m < 0.f) ? -1.f : 0.f);
                #pragma unroll
                for (int j = 0; j < 16; j++) m16[j] += sgn * sf[732 + k * 16 + j];
            }
        }
        #pragma unroll
        for (int j = 0; j < 16; j++) {
            m16[j] += __shfl_xor_sync(0xffffffffu, m16[j], 1);
            m16[j] += __shfl_xor_sync(0xffffffffu, m16[j], 2);
        }

        int idx = 0;
        {
            float bm = m16[0];
            #pragma unroll
            for (int j = 1; j < 16; j++)
                if (m16[j] > bm) { bm = m16[j]; idx = j; }   // first-max
        }

        unsigned code = 0;
        #pragma unroll
        for (int h = 0; h < 8; h++)
            code |= (unsigned)(__shfl_sync(0xffffffffu, idx, h * 4) & 15) << (4 * h);
        if (lane == 0) g_code[b] = code;

        phase_done(tid, &c_idx);

    } else if (bx < NB_GEMV + NB_IDX + NB_K2) {
        // ==================== K2: build V table ==============================
        phase_wait2(tid, &c_gemv, NB_GEMV, &c_idx, NB_IDX);

        float* sr   = (float*)sW4;          // 96*16 floats
        float* sLUT = ((float*)sW4) + 1536; // 64 floats
        const int lb = bx - (NB_GEMV + NB_IDX);
        const int c  = lb >> 5;
        const int n0 = (lb & 31) * 8;

        if (tid < 64) sLUT[tid] = LUT[c * 64 + tid];
        __syncthreads();

        if (tid < 96) {
            int nl = tid / 12, kk = tid % 12;
            int nkk = (n0 + nl) * 12 + kk;
            float v0 = g_WeFp[nkk]           + g_WeFp[5 * NKK + nkk];
            float v1 = g_WeFp[NKK + nkk]     + g_WeFp[6 * NKK + nkk];
            float v2 = g_WeFp[2 * NKK + nkk] + g_WeFp[7 * NKK + nkk];
            float v3 = g_WeFp[3 * NKK + nkk] + g_WeFp[8 * NKK + nkk];
            float v4 = g_WeFp[4 * NKK + nkk] + g_WeFp[9 * NKK + nkk];
            #pragma unroll
            for (int j = 0; j < 16; j++) {
                float r = sLUT[j * 4] * v0 + sLUT[j * 4 + 1] * v1 +
                          sLUT[j * 4 + 2] * v2 + sLUT[j * 4 + 3] * v3 + v4;
                sr[tid * 16 + j] = fmaxf(r, 0.f);
            }
        }
        __syncthreads();

        if (tid < NCLS) {
            const int cls = tid;
            float vac[16];
            #pragma unroll
            for (int j = 0; j < 16; j++) vac[j] = 0.f;

            #pragma unroll
            for (int K = 3; K <= 5; K++) {
                const int off = (K == 3) ? 0 : ((K == 4) ? 1536 : 2816);
                const int P   = 9 - K;
                const int kk0 = (K == 3) ? 0 : ((K == 4) ? 3 : 7);
                #pragma unroll
                for (int k = 0; k < 5; k++) {
                    if (k >= K) break;
                    int p = c - k;
                    if (p < 0 || p > P - 1) continue;
                    int kk = kk0 + k;
                    #pragma unroll
                    for (int nl = 0; nl < 8; nl++) {
                        int feat = off + (n0 + nl) * P + p;
                        float w2 = W2[feat * NCLS + cls];
                        const float4* r4 = (const float4*)&sr[(nl * 12 + kk) * 16];
                        float4 a = r4[0], b = r4[1], cc = r4[2], d = r4[3];
                        vac[0]  += a.x * w2;  vac[1]  += a.y * w2;
                        vac[2]  += a.z * w2;  vac[3]  += a.w * w2;
                        vac[4]  += b.x * w2;  vac[5]  += b.y * w2;
                        vac[6]  += b.z * w2;  vac[7]  += b.w * w2;
                        vac[8]  += cc.x * w2; vac[9]  += cc.y * w2;
                        vac[10] += cc.z * w2; vac[11] += cc.w * w2;
                        vac[12] += d.x * w2;  vac[13] += d.y * w2;
                        vac[14] += d.z * w2;  vac[15] += d.w * w2;
                    }
                }
            }
            #pragma unroll
            for (int j = 0; j < 16; j++)
                atomicAdd(&g_V[(c * 16 + j) * NCLS + cls], vac[j]);
        }

        phase_done(tid, &c_k2);

    } else {
        // ==================== K3: gather + log_softmax =======================
        phase_wait2(tid, &c_k2, NB_K2, &c_k2, NB_K2);

        const int b = (bx - (NB_GEMV + NB_IDX + NB_K2)) * 4 + warp;

        const unsigned code = g_code[b];
        int vrow[8];
        #pragma unroll
        for (int h = 0; h < 8; h++)
            vrow[h] = (h * 16 + (int)((code >> (4 * h)) & 15u)) * NCLS;

        float4 a;
        float M;
        if (lane < 25) {
            a = ((const float4*)b2)[lane];
            #pragma unroll
            for (int h = 0; h < 8; h++) {
                const float4 v = *(const float4*)(g_V + vrow[h] + 4 * lane);
                a.x += v.x; a.y += v.y; a.z += v.z; a.w += v.w;
            }
            M = fmaxf(fmaxf(a.x, a.y), fmaxf(a.z, a.w));
        } else {
            a = make_float4(0.f, 0.f, 0.f, 0.f);
            M = -INFINITY;
        }

        #pragma unroll
        for (int off = 16; off > 0; off >>= 1)
            M = fmaxf(M, __shfl_xor_sync(0xffffffffu, M, off));

        float ss = 0.f;
        if (lane < 25)
            ss = expf(a.x - M) + expf(a.y - M) + expf(a.z - M) + expf(a.w - M);
        #pragma unroll
        for (int off = 16; off > 0; off >>= 1)
            ss += __shfl_xor_sync(0xffffffffu, ss, off);

        const float lse = M + logf(ss);
        if (lane < 25) {
            float4 o = make_float4(a.x - lse, a.y - lse, a.z - lse, a.w - lse);
            *(float4*)(out + (size_t)b * NCLS + 4 * lane) = o;
        }
        __syncthreads();
    }

    // -------- exit protocol: last block resets counters for next replay -----
    if (tid == 0) {
        __threadfence();
        int e = atomicAdd(&c_exit, 1);
        if (e == NB_TOT - 1) {
            c_gemv = 0; c_idx = 0; c_k2 = 0; c_exit = 0;
        }
    }
}

// ---------------------------------------------------------------------------
extern "C" void kernel_launch(void* const* d_in, const int* in_sizes, int n_in,
                              void* d_out, int out_size)
{
    (void)in_sizes; (void)n_in; (void)out_size;
    const void*  x       = d_in[0];
    const float* len_emb = (const float*)d_in[1];
    const float* ipd_emb = (const float*)d_in[2];
    const float* W1      = (const float*)d_in[3];
    const float* b1      = (const float*)d_in[4];
    const float* We      = (const float*)d_in[5];
    const float* be      = (const float*)d_in[6];
    const float* w3      = (const float*)d_in[7];
    const float* w4      = (const float*)d_in[8];
    const float* w5      = (const float*)d_in[9];
    const float* W2      = (const float*)d_in[10];
    const float* b2      = (const float*)d_in[11];
    const float* S       = (const float*)d_in[12];
    const float* H       = (const float*)d_in[13];
    const float* T       = (const float*)d_in[14];
    const float* LUT     = (const float*)d_in[15];
    float* out = (float*)d_out;

    mega<<<NB_TOT, 128>>>(We, be, w3, w4, w5, x,
                          len_emb, ipd_emb, W1, b1, S, T, H,
                          LUT, W2, b2, out);
}

// round 14
// speedup vs baseline: 1.4381x; 1.4381x over previous
#include <cuda_runtime.h>
#include <math.h>

// ---------------------------------------------------------------------------
//  B=4096, SEQ=C=8, D=4, L=2048, NK=256, NCLS=100
//  filters: w3 (256,3,2048), w4 (256,4,2048), w5 (256,5,2048) -> 3072 rows
// ---------------------------------------------------------------------------

#define NKK 3072
#define NCLS 100

__device__ float    g_WeFp[2 * 5 * NKK];            // [half][d][nkk]; d=4 = be
__device__ __align__(16) float g_V[8 * 16 * NCLS];  // 16B-aligned for float4
__device__ unsigned g_code[4096];                   // packed idx: 8 x 4 bits

// ---------------------------------------------------------------------------
// K1: streaming GEMV (round-8 structure, 9.6us measured) + g_V zeroing.
//     384 blocks x 128 thr; warp owns 4 rows x one 1024-float L-half.
// ---------------------------------------------------------------------------
__global__ void __launch_bounds__(128, 4)
k1_wef(const float* __restrict__ We, const float* __restrict__ be,
       const float* __restrict__ w3, const float* __restrict__ w4,
       const float* __restrict__ w5)
{
    __shared__ float4 sW4[5 * 256];   // 20 KB
    const int tid  = threadIdx.x;
    const int lane = tid & 31;
    const int warp = tid >> 5;
    const int grp  = blockIdx.x >> 1;
    const int ch   = blockIdx.x & 1;
    const int r0   = grp * 16 + warp * 4;

    {   // zero g_V (12800 floats; first 100 blocks, 1 store/thread)
        int gz = blockIdx.x * 128 + tid;
        if (gz < 8 * 16 * NCLS) g_V[gz] = 0.f;
    }

    const float4* rp[4];
    #pragma unroll
    for (int r = 0; r < 4; r++) {
        int rid = r0 + r;
        int n = rid / 12, kk = rid % 12;
        const float* base;
        if (kk < 3)      base = w3 + (size_t)(n * 3 + kk) * 2048;
        else if (kk < 7) base = w4 + (size_t)(n * 4 + (kk - 3)) * 2048;
        else             base = w5 + (size_t)(n * 5 + (kk - 7)) * 2048;
        rp[r] = (const float4*)base + ch * 256;
    }

    float4 bufA[4], bufB[4];
    #pragma unroll
    for (int r = 0; r < 4; r++) bufA[r] = rp[r][lane];

    const float4* We4 = (const float4*)We;
    const float4* be4 = (const float4*)be;
    #pragma unroll
    for (int i = 0; i < 2; i++) {
        const int p = tid + 128 * i;
        sW4[p]        = We4[ch * 256 + p];
        sW4[256 + p]  = We4[512 + ch * 256 + p];
        sW4[512 + p]  = We4[1024 + ch * 256 + p];
        sW4[768 + p]  = We4[1536 + ch * 256 + p];
        sW4[1024 + p] = be4[ch * 256 + p];
    }
    __syncthreads();

    float acc[4][5];
    #pragma unroll
    for (int r = 0; r < 4; r++)
        #pragma unroll
        for (int d = 0; d < 5; d++) acc[r][d] = 0.f;

    #pragma unroll
    for (int i = 0; i < 8; i++) {
        float4* cur = (i & 1) ? bufB : bufA;
        float4* nxt = (i & 1) ? bufA : bufB;
        if (i < 7) {
            const int o = (i + 1) * 32 + lane;
            #pragma unroll
            for (int r = 0; r < 4; r++) nxt[r] = rp[r][o];
        }
        const int l = i * 32 + lane;
        #pragma unroll
        for (int d = 0; d < 5; d++) {
            float4 s = sW4[d * 256 + l];
            #pragma unroll
            for (int r = 0; r < 4; r++)
                acc[r][d] += cur[r].x * s.x + cur[r].y * s.y
                           + cur[r].z * s.z + cur[r].w * s.w;
        }
    }

    #pragma unroll
    for (int r = 0; r < 4; r++)
        #pragma unroll
        for (int d = 0; d < 5; d++) {
            float a = acc[r][d];
            #pragma unroll
            for (int w = 16; w > 0; w >>= 1)
                a += __shfl_down_sync(0xffffffffu, a, w);
            if (lane == 0)
                g_WeFp[ch * 5 * NKK + d * NKK + (r0 + r)] = a;
        }
}

// ---------------------------------------------------------------------------
// KB: heterogeneous. blocks [0,256): K2 V-table build (atomics into zeroed
//     g_V); blocks [256,1280): idx codes (4 batch rows per block).
//     Both independent; idx blocks don't read g_WeFp.
// ---------------------------------------------------------------------------
__global__ void __launch_bounds__(128)
kB(const float* __restrict__ LUT, const float* __restrict__ W2,
   const void* __restrict__ xraw,
   const float* __restrict__ len_emb, const float* __restrict__ ipd_emb,
   const float* __restrict__ W1, const float* __restrict__ b1,
   const float* __restrict__ S,  const float* __restrict__ T,
   const float* __restrict__ H)
{
    __shared__ float sf[1600];   // k2: sr[1536]+sLUT[64]; idx: [0:972)
    const int tid  = threadIdx.x;
    const int lane = tid & 31;
    const int warp = tid >> 5;

    if (blockIdx.x < 256) {
        // ==================== K2 path =======================================
        float* sr   = sf;
        float* sLUT = sf + 1536;
        const int c  = blockIdx.x >> 5;
        const int n0 = (blockIdx.x & 31) * 8;

        if (tid < 64) sLUT[tid] = LUT[c * 64 + tid];
        __syncthreads();

        if (tid < 96) {
            int nl = tid / 12, kk = tid % 12;
            int nkk = (n0 + nl) * 12 + kk;
            float v0 = g_WeFp[nkk]           + g_WeFp[5 * NKK + nkk];
            float v1 = g_WeFp[NKK + nkk]     + g_WeFp[6 * NKK + nkk];
            float v2 = g_WeFp[2 * NKK + nkk] + g_WeFp[7 * NKK + nkk];
            float v3 = g_WeFp[3 * NKK + nkk] + g_WeFp[8 * NKK + nkk];
            float v4 = g_WeFp[4 * NKK + nkk] + g_WeFp[9 * NKK + nkk];
            #pragma unroll
            for (int j = 0; j < 16; j++) {
                float r = sLUT[j * 4] * v0 + sLUT[j * 4 + 1] * v1 +
                          sLUT[j * 4 + 2] * v2 + sLUT[j * 4 + 3] * v3 + v4;
                sr[tid * 16 + j] = fmaxf(r, 0.f);
            }
        }
        __syncthreads();

        if (tid < NCLS) {
            const int cls = tid;
            float vac[16];
            #pragma unroll
            for (int j = 0; j < 16; j++) vac[j] = 0.f;

            #pragma unroll
            for (int K = 3; K <= 5; K++) {
                const int off = (K == 3) ? 0 : ((K == 4) ? 1536 : 2816);
                const int P   = 9 - K;
                const int kk0 = (K == 3) ? 0 : ((K == 4) ? 3 : 7);
                #pragma unroll
                for (int k = 0; k < 5; k++) {
                    if (k >= K) break;
                    int p = c - k;
                    if (p < 0 || p > P - 1) continue;
                    int kk = kk0 + k;
                    #pragma unroll
                    for (int nl = 0; nl < 8; nl++) {
                        int feat = off + (n0 + nl) * P + p;
                        float w2 = W2[feat * NCLS + cls];
                        const float4* r4 = (const float4*)&sr[(nl * 12 + kk) * 16];
                        float4 a = r4[0], b = r4[1], cc = r4[2], d = r4[3];
                        vac[0]  += a.x * w2;  vac[1]  += a.y * w2;
                        vac[2]  += a.z * w2;  vac[3]  += a.w * w2;
                        vac[4]  += b.x * w2;  vac[5]  += b.y * w2;
                        vac[6]  += b.z * w2;  vac[7]  += b.w * w2;
                        vac[8]  += cc.x * w2; vac[9]  += cc.y * w2;
                        vac[10] += cc.z * w2; vac[11] += cc.w * w2;
                        vac[12] += d.x * w2;  vac[13] += d.y * w2;
                        vac[14] += d.z * w2;  vac[15] += d.w * w2;
                    }
                }
            }
            #pragma unroll
            for (int j = 0; j < 16; j++)
                atomicAdd(&g_V[(c * 16 + j) * NCLS + cls], vac[j]);
        }
    } else {
        // ==================== idx path (4 rows per block) ====================
        // sf layout: [0:128) W1, [128:132) b1, [132:612) S, [612:732) T,
        //            [732:972) H
        sf[tid] = W1[tid];
        if (tid < 4) sf[128 + tid] = b1[tid];
        #pragma unroll
        for (int i = 0; i < 4; i++) {
            int p = tid + 128 * i;
            if (p < 480) sf[132 + p] = S[p];
        }
        if (tid < 120) sf[612 + tid] = T[tid];
        sf[732 + tid] = H[tid];
        if (tid < 112) sf[860 + tid] = H[128 + tid];
        __syncthreads();

        const int b = (blockIdx.x - 256) * 4 + warp;   // 0..4095

        const int* xi = (const int*)xraw;
        int any = 0;
        #pragma unroll
        for (int j = 0; j < 4; j++) any |= xi[1 + 2 * (lane + 32 * j)];
        const int is64 = __any_sync(0xffffffffu, any != 0) ? 0 : 1;

        const int c = lane >> 2;
        const int q = lane & 3;

        int i0, i1;
        if (is64) {
            const long long* xp = (const long long*)xraw;
            i0 = (int)xp[((size_t)b * 8 + c) * 2];
            i1 = (int)xp[((size_t)b * 8 + c) * 2 + 1];
        } else {
            const int* xp = (const int*)xraw;
            i0 = xp[((size_t)b * 8 + c) * 2];
            i1 = xp[((size_t)b * 8 + c) * 2 + 1];
        }

        float4 vl = ((const float4*)(len_emb + (size_t)i0 * 16))[q];
        float4 vi = ((const float4*)(ipd_emb + (size_t)i1 * 16))[q];

        float h4[4] = {0.f, 0.f, 0.f, 0.f};
        {
            const float lv[4] = {vl.x, vl.y, vl.z, vl.w};
            const float iv[4] = {vi.x, vi.y, vi.z, vi.w};
            #pragma unroll
            for (int s = 0; s < 4; s++) {
                const int il = q * 4 + s;
                const int ii = 16 + q * 4 + s;
                #pragma unroll
                for (int d = 0; d < 4; d++) {
                    h4[d] += lv[s] * sf[il * 4 + d];
                    h4[d] += iv[s] * sf[ii * 4 + d];
                }
            }
        }
        #pragma unroll
        for (int d = 0; d < 4; d++) {
            h4[d] += __shfl_xor_sync(0xffffffffu, h4[d], 1);
            h4[d] += __shfl_xor_sync(0xffffffffu, h4[d], 2);
            h4[d] += sf[128 + d];
        }

        float m16[16];
        #pragma unroll
        for (int j = 0; j < 16; j++) m16[j] = 0.f;

        #pragma unroll
        for (int kq = 0; kq < 4; kq++) {
            const int k = q + kq * 4;
            if (k < 15) {
                float a = 0.f;
                #pragma unroll
                for (int d = 0; d < 4; d++)
                    a += h4[d] * sf[132 + (c * 4 + d) * 15 + k];
                float m = (a - sf[612 + c * 15 + k]) - 1e-4f;
                float sgn = (m > 0.f) ? 1.f : ((m < 0.f) ? -1.f : 0.f);
                #pragma unroll
                for (int j = 0; j < 16; j++) m16[j] += sgn * sf[732 + k * 16 + j];
            }
        }
        #pragma unroll
        for (int j = 0; j < 16; j++) {
            m16[j] += __shfl_xor_sync(0xffffffffu, m16[j], 1);
            m16[j] += __shfl_xor_sync(0xffffffffu, m16[j], 2);
        }

        int idx = 0;
        {
            float bm = m16[0];
            #pragma unroll
            for (int j = 1; j < 16; j++)
                if (m16[j] > bm) { bm = m16[j]; idx = j; }   // first-max
        }

        unsigned code = 0;
        #pragma unroll
        for (int h = 0; h < 8; h++)
            code |= (unsigned)(__shfl_sync(0xffffffffu, idx, h * 4) & 15) << (4 * h);
        if (lane == 0) g_code[b] = code;
    }
}

// ---------------------------------------------------------------------------
// K3: vectorized gather + log_softmax. One warp per b; 25 lanes x float4.
// ---------------------------------------------------------------------------
__global__ void k3_main(const float* __restrict__ b2, float* __restrict__ out)
{
    __shared__ float4 sb2[25];
    const int tid = threadIdx.x;
    if (tid < 25) sb2[tid] = ((const float4*)b2)[tid];
    __syncthreads();

    const int warp = tid >> 5, lane = tid & 31;
    const int b = blockIdx.x * 8 + warp;

    const unsigned code = g_code[b];
    int vrow[8];
    #pragma unroll
    for (int h = 0; h < 8; h++)
        vrow[h] = (h * 16 + (int)((code >> (4 * h)) & 15u)) * NCLS;

    float4 a;
    float M;
    if (lane < 25) {
        a = sb2[lane];
        #pragma unroll
        for (int h = 0; h < 8; h++) {
            const float4 v = *(const float4*)(g_V + vrow[h] + 4 * lane);
            a.x += v.x; a.y += v.y; a.z += v.z; a.w += v.w;
        }
        M = fmaxf(fmaxf(a.x, a.y), fmaxf(a.z, a.w));
    } else {
        a = make_float4(0.f, 0.f, 0.f, 0.f);
        M = -INFINITY;
    }

    #pragma unroll
    for (int off = 16; off > 0; off >>= 1)
        M = fmaxf(M, __shfl_xor_sync(0xffffffffu, M, off));

    float ss = 0.f;
    if (lane < 25)
        ss = expf(a.x - M) + expf(a.y - M) + expf(a.z - M) + expf(a.w - M);
    #pragma unroll
    for (int off = 16; off > 0; off >>= 1)
        ss += __shfl_xor_sync(0xffffffffu, ss, off);

    const float lse = M + logf(ss);
    if (lane < 25) {
        float4 o = make_float4(a.x - lse, a.y - lse, a.z - lse, a.w - lse);
        *(float4*)(out + (size_t)b * NCLS + 4 * lane) = o;
    }
}

// ---------------------------------------------------------------------------
extern "C" void kernel_launch(void* const* d_in, const int* in_sizes, int n_in,
                              void* d_out, int out_size)
{
    (void)in_sizes; (void)n_in; (void)out_size;
    const void*  x       = d_in[0];
    const float* len_emb = (const float*)d_in[1];
    const float* ipd_emb = (const float*)d_in[2];
    const float* W1      = (const float*)d_in[3];
    const float* b1      = (const float*)d_in[4];
    const float* We      = (const float*)d_in[5];
    const float* be      = (const float*)d_in[6];
    const float* w3      = (const float*)d_in[7];
    const float* w4      = (const float*)d_in[8];
    const float* w5      = (const float*)d_in[9];
    const float* W2      = (const float*)d_in[10];
    const float* b2      = (const float*)d_in[11];
    const float* S       = (const float*)d_in[12];
    const float* H       = (const float*)d_in[13];
    const float* T       = (const float*)d_in[14];
    const float* LUT     = (const float*)d_in[15];
    float* out = (float*)d_out;

    k1_wef<<<384, 128>>>(We, be, w3, w4, w5);
    kB<<<1280, 128>>>(LUT, W2, x, len_emb, ipd_emb, W1, b1, S, T, H);
    k3_main<<<512, 256>>>(b2, out);
}